// round 1
// baseline (speedup 1.0000x reference)
#include <cuda_runtime.h>
#include <cuda_bf16.h>

#define T_DIM 1024
#define B_DIM 64
#define H_DIM 1024
#define OSPLIT 32            // o-range of 32 per k1 block

// Scratch (allocation-free rule: __device__ globals)
__device__ float g_partial[OSPLIT * B_DIM * H_DIM];  // 8 MB: [s][b][h]
__device__ float g_v[B_DIM * H_DIM];                 // 256 KB
__device__ float g_energies[B_DIM * T_DIM];          // 256 KB: [b][t]

// ---------------------------------------------------------------------------
// k1: partial[s][b][h] = sum_{o in s-range} hid[b][o] * W[o][h]
// grid (H/256 h-tiles, 32 o-splits, 2 b-groups), 256 threads
// ---------------------------------------------------------------------------
__global__ void __launch_bounds__(256) k1_proj_partial(
    const float* __restrict__ hid, const float* __restrict__ W)
{
    const int h  = blockIdx.x * 256 + threadIdx.x;
    const int o0 = blockIdx.y * OSPLIT;
    const int b0 = blockIdx.z * 32;

    __shared__ float sh[32 * OSPLIT];  // sh[bb][oo]
    for (int i = threadIdx.x; i < 32 * OSPLIT; i += 256) {
        int bb = i >> 5;
        int oo = i & 31;
        sh[i] = hid[(b0 + bb) * H_DIM + o0 + oo];
    }
    __syncthreads();

    // Preload this thread's W column slice (coalesced across threads)
    float w[OSPLIT];
#pragma unroll
    for (int oo = 0; oo < OSPLIT; oo++)
        w[oo] = W[(o0 + oo) * H_DIM + h];

    float* part = g_partial + blockIdx.y * (B_DIM * H_DIM) + h;

#pragma unroll
    for (int bb = 0; bb < 32; bb++) {
        const float4* s4 = reinterpret_cast<const float4*>(sh + bb * OSPLIT);
        float acc = 0.f;
#pragma unroll
        for (int q = 0; q < OSPLIT / 4; q++) {
            float4 x = s4[q];
            acc += x.x * w[4 * q + 0] + x.y * w[4 * q + 1]
                 + x.z * w[4 * q + 2] + x.w * w[4 * q + 3];
        }
        part[(b0 + bb) * H_DIM] = acc;
    }
}

// ---------------------------------------------------------------------------
// k1b: v[i] = sum_s partial[s][i]   (deterministic reduction, no atomics)
// ---------------------------------------------------------------------------
__global__ void __launch_bounds__(256) k1b_reduce()
{
    int i = blockIdx.x * 256 + threadIdx.x;  // 65536 total
    float s = 0.f;
#pragma unroll
    for (int p = 0; p < OSPLIT; p++)
        s += g_partial[p * (B_DIM * H_DIM) + i];
    g_v[i] = s;
}

// ---------------------------------------------------------------------------
// k2: energies[b][t] = <enc[t,b,:], v[b,:]>   one warp per (t,b)
// enc rows are 4 KB contiguous; v is L2-resident (256 KB). Streams 256 MB.
// ---------------------------------------------------------------------------
__global__ void __launch_bounds__(256) k2_energies(const float* __restrict__ enc)
{
    const int gw   = (blockIdx.x * blockDim.x + threadIdx.x) >> 5;  // global warp
    const int lane = threadIdx.x & 31;
    const int b = gw & (B_DIM - 1);
    const int t = gw >> 6;

    const float4* e4 = reinterpret_cast<const float4*>(
        enc + (size_t)(t * B_DIM + b) * H_DIM);
    const float4* v4 = reinterpret_cast<const float4*>(g_v + b * H_DIM);

    float acc = 0.f;
#pragma unroll
    for (int k = 0; k < H_DIM / (32 * 4); k++) {   // 8 iterations
        float4 x = e4[lane + 32 * k];
        float4 y = v4[lane + 32 * k];
        acc += x.x * y.x + x.y * y.y + x.z * y.z + x.w * y.w;
    }
#pragma unroll
    for (int off = 16; off; off >>= 1)
        acc += __shfl_xor_sync(0xffffffffu, acc, off);
    if (lane == 0)
        g_energies[b * T_DIM + t] = acc;
}

// ---------------------------------------------------------------------------
// k3: row softmax over T (max-shifted; bias term c[b] drops out by invariance)
// one block per b, 256 threads x 4 elements
// ---------------------------------------------------------------------------
__global__ void __launch_bounds__(256) k3_softmax(float* __restrict__ out)
{
    const int b   = blockIdx.x;
    const int tid = threadIdx.x;
    __shared__ float red[256];

    float vals[4];
#pragma unroll
    for (int i = 0; i < 4; i++)
        vals[i] = g_energies[b * T_DIM + tid + i * 256];

    float m = fmaxf(fmaxf(vals[0], vals[1]), fmaxf(vals[2], vals[3]));
    red[tid] = m;
    __syncthreads();
    for (int s = 128; s > 0; s >>= 1) {
        if (tid < s) red[tid] = fmaxf(red[tid], red[tid + s]);
        __syncthreads();
    }
    m = red[0];
    __syncthreads();

    float e[4];
    float lsum = 0.f;
#pragma unroll
    for (int i = 0; i < 4; i++) {
        e[i] = __expf(vals[i] - m);
        lsum += e[i];
    }
    red[tid] = lsum;
    __syncthreads();
    for (int s = 128; s > 0; s >>= 1) {
        if (tid < s) red[tid] += red[tid + s];
        __syncthreads();
    }
    float inv = 1.f / red[0];

#pragma unroll
    for (int i = 0; i < 4; i++)
        out[b * T_DIM + tid + i * 256] = e[i] * inv;
}

// ---------------------------------------------------------------------------
extern "C" void kernel_launch(void* const* d_in, const int* in_sizes, int n_in,
                              void* d_out, int out_size)
{
    const float* hid = (const float*)d_in[0];   // [1, B, H]
    const float* enc = (const float*)d_in[1];   // [T, B, H]
    const float* W   = (const float*)d_in[2];   // [H, H]
    // d_in[3] = bias: dropped — softmax shift-invariance makes it a no-op.
    float* out = (float*)d_out;                 // [B, 1, T]

    k1_proj_partial<<<dim3(H_DIM / 256, OSPLIT, 2), 256>>>(hid, W);
    k1b_reduce<<<(B_DIM * H_DIM) / 256, 256>>>();
    k2_energies<<<(T_DIM * B_DIM * 32) / 256, 256>>>(enc);
    k3_softmax<<<B_DIM, 256>>>(out);
}

// round 3
// speedup vs baseline: 1.1368x; 1.1368x over previous
#include <cuda_runtime.h>
#include <cuda_bf16.h>

#define T_DIM 1024
#define B_DIM 64
#define H_DIM 1024
#define OSPLIT 32            // o-range of 32 per k1 block
#define TPW 16               // t-rows per warp in k2

// Scratch (allocation-free rule: __device__ globals)
__device__ float g_partial[OSPLIT * B_DIM * H_DIM];  // 8 MB: [s][b][h]
__device__ float g_v[B_DIM * H_DIM];                 // 256 KB
__device__ float g_energies[B_DIM * T_DIM];          // 256 KB: [b][t]

// ---------------------------------------------------------------------------
// k1: partial[s][b][h] = sum_{o in s-range} hid[b][o] * W[o][h]
// grid (H/256 h-tiles, 32 o-splits, 2 b-groups), 256 threads. W read once.
// ---------------------------------------------------------------------------
__global__ void __launch_bounds__(256) k1_proj_partial(
    const float* __restrict__ hid, const float* __restrict__ W)
{
    const int h  = blockIdx.x * 256 + threadIdx.x;
    const int o0 = blockIdx.y * OSPLIT;
    const int b0 = blockIdx.z * 32;

    __shared__ float sh[32 * OSPLIT];  // sh[bb][oo]
    for (int i = threadIdx.x; i < 32 * OSPLIT; i += 256) {
        int bb = i >> 5;
        int oo = i & 31;
        sh[i] = hid[(b0 + bb) * H_DIM + o0 + oo];
    }
    __syncthreads();

    float w[OSPLIT];
#pragma unroll
    for (int oo = 0; oo < OSPLIT; oo++)
        w[oo] = W[(o0 + oo) * H_DIM + h];

    float* part = g_partial + blockIdx.y * (B_DIM * H_DIM) + h;

#pragma unroll
    for (int bb = 0; bb < 32; bb++) {
        const float4* s4 = reinterpret_cast<const float4*>(sh + bb * OSPLIT);
        float acc = 0.f;
#pragma unroll
        for (int q = 0; q < OSPLIT / 4; q++) {
            float4 x = s4[q];
            acc += x.x * w[4 * q + 0] + x.y * w[4 * q + 1]
                 + x.z * w[4 * q + 2] + x.w * w[4 * q + 3];
        }
        part[(b0 + bb) * H_DIM] = acc;
    }
}

// ---------------------------------------------------------------------------
// k1b: v[i] = sum_s partial[s][i]   (deterministic reduction, no atomics)
// ---------------------------------------------------------------------------
__global__ void __launch_bounds__(256) k1b_reduce()
{
    int i = blockIdx.x * 256 + threadIdx.x;  // 65536 total
    float s = 0.f;
#pragma unroll
    for (int p = 0; p < OSPLIT; p++)
        s += g_partial[p * (B_DIM * H_DIM) + i];
    g_v[i] = s;
}

// ---------------------------------------------------------------------------
// k2: energies[b][t] = <enc[t,b,:], v[b,:]>
// One warp owns one b and TPW consecutive t-rows. v[b] lives in 32 registers
// per lane (8 float4) — loaded ONCE per warp, so L2 traffic is enc-only.
// grid = 64 b  x  T/(8*TPW) t-chunks, 256 threads (8 warps).
// ---------------------------------------------------------------------------
__global__ void __launch_bounds__(256) k2_energies(const float* __restrict__ enc)
{
    const int warp = threadIdx.x >> 5;
    const int lane = threadIdx.x & 31;
    const int b    = blockIdx.x;                       // 0..63
    const int t0   = blockIdx.y * (8 * TPW) + warp * TPW;

    // v[b] -> registers (one-time 4 KB load per warp, L2-hot)
    const float4* v4 = reinterpret_cast<const float4*>(g_v + b * H_DIM);
    float4 v[8];
#pragma unroll
    for (int k = 0; k < 8; k++)
        v[k] = v4[lane + 32 * k];

    // Row pointer for first t; advance by a constant row stride per iter
    const float4* e4 = reinterpret_cast<const float4*>(
        enc + (size_t)(t0 * B_DIM + b) * H_DIM) + lane;
    const size_t row_stride4 = (size_t)B_DIM * H_DIM / 4;   // in float4 units

    float* eout = g_energies + b * T_DIM + t0;

#pragma unroll 4
    for (int i = 0; i < TPW; i++) {
        float acc = 0.f;
#pragma unroll
        for (int k = 0; k < 8; k++) {
            float4 x = e4[32 * k];
            acc += x.x * v[k].x + x.y * v[k].y + x.z * v[k].z + x.w * v[k].w;
        }
#pragma unroll
        for (int off = 16; off; off >>= 1)
            acc += __shfl_xor_sync(0xffffffffu, acc, off);
        if (lane == 0)
            eout[i] = acc;
        e4 += row_stride4;
    }
}

// ---------------------------------------------------------------------------
// k3: softmax over T per row b — one warp per row, all-shuffle reductions.
// Each lane holds 32 values (8 float4). Bias dropped (shift invariance).
// grid = 8 blocks x 256 threads = 64 warps.
// ---------------------------------------------------------------------------
__global__ void __launch_bounds__(256) k3_softmax(float* __restrict__ out)
{
    const int warp = threadIdx.x >> 5;
    const int lane = threadIdx.x & 31;
    const int b    = blockIdx.x * 8 + warp;

    const float4* e4 = reinterpret_cast<const float4*>(g_energies + b * T_DIM);
    float4 vals[8];
#pragma unroll
    for (int k = 0; k < 8; k++)
        vals[k] = e4[lane + 32 * k];

    float m = -1e30f;
#pragma unroll
    for (int k = 0; k < 8; k++)
        m = fmaxf(m, fmaxf(fmaxf(vals[k].x, vals[k].y), fmaxf(vals[k].z, vals[k].w)));
#pragma unroll
    for (int off = 16; off; off >>= 1)
        m = fmaxf(m, __shfl_xor_sync(0xffffffffu, m, off));

    float lsum = 0.f;
#pragma unroll
    for (int k = 0; k < 8; k++) {
        vals[k].x = __expf(vals[k].x - m);
        vals[k].y = __expf(vals[k].y - m);
        vals[k].z = __expf(vals[k].z - m);
        vals[k].w = __expf(vals[k].w - m);
        lsum += vals[k].x + vals[k].y + vals[k].z + vals[k].w;
    }
#pragma unroll
    for (int off = 16; off; off >>= 1)
        lsum += __shfl_xor_sync(0xffffffffu, lsum, off);
    const float inv = 1.f / lsum;

    float4* o4 = reinterpret_cast<float4*>(out + b * T_DIM);
#pragma unroll
    for (int k = 0; k < 8; k++) {
        float4 r = vals[k];
        r.x *= inv; r.y *= inv; r.z *= inv; r.w *= inv;
        o4[lane + 32 * k] = r;
    }
}

// ---------------------------------------------------------------------------
extern "C" void kernel_launch(void* const* d_in, const int* in_sizes, int n_in,
                              void* d_out, int out_size)
{
    const float* hid = (const float*)d_in[0];   // [1, B, H]
    const float* enc = (const float*)d_in[1];   // [T, B, H]
    const float* W   = (const float*)d_in[2];   // [H, H]
    // d_in[3] = bias: dropped — softmax shift-invariance makes it a no-op.
    float* out = (float*)d_out;                 // [B, 1, T]

    k1_proj_partial<<<dim3(H_DIM / 256, OSPLIT, 2), 256>>>(hid, W);
    k1b_reduce<<<(B_DIM * H_DIM) / 256, 256>>>();
    k2_energies<<<dim3(B_DIM, T_DIM / (8 * TPW)), 256>>>(enc);
    k3_softmax<<<B_DIM / 8, 256>>>(out);
}